// round 3
// baseline (speedup 1.0000x reference)
#include <cuda_runtime.h>
#include <cuda_bf16.h>

#define MARGIN   0.1f
#define BEPS     1e-5f
#define AEPS     1e-7f

#define MAXB 4608
#define MAXC 10240

static __device__ double g_hsum;
static __device__ float  g_pn[MAXB];     // clipped ||pred||^2
static __device__ float  g_cb[MAXB];     // 2/(1-pn)
static __device__ float  g_scorr[MAXB];  // dist2correct + MARGIN
static __device__ float  g_an[MAXC];     // clipped ||all||^2
static __device__ float  g_ca[MAXC];     // 1/(1-an)

// ---------------- prep: 8 threads per row, shfl-reduced ----------------
__global__ void prep_kernel(const float* __restrict__ pred,
                            const float* __restrict__ tgt,
                            const float* __restrict__ all,
                            int B, int C) {
    int gid  = blockIdx.x * blockDim.x + threadIdx.x;
    int r    = gid >> 3;
    int lane = gid & 7;
    if (gid == 0) g_hsum = 0.0;

    if (r < C) {
        const float4* a4 = (const float4*)(all + (size_t)r * 64) + lane * 2;
        float s = 0.f;
#pragma unroll
        for (int j = 0; j < 2; j++) {
            float4 v = a4[j];
            s = fmaf(v.x, v.x, s); s = fmaf(v.y, v.y, s);
            s = fmaf(v.z, v.z, s); s = fmaf(v.w, v.w, s);
        }
        s += __shfl_xor_sync(0xFFFFFFFFu, s, 1);
        s += __shfl_xor_sync(0xFFFFFFFFu, s, 2);
        s += __shfl_xor_sync(0xFFFFFFFFu, s, 4);
        if (lane == 0) {
            s = fminf(fmaxf(s, 0.f), 1.0f - BEPS);
            g_an[r] = s;
            g_ca[r] = 1.0f / (1.0f - s);
        }
    }

    if (r < B) {
        const float4* p4 = (const float4*)(pred + (size_t)r * 64) + lane * 2;
        const float4* t4 = (const float4*)(tgt  + (size_t)r * 64) + lane * 2;
        float pn = 0.f, tn = 0.f, sq = 0.f;
#pragma unroll
        for (int j = 0; j < 2; j++) {
            float4 p = p4[j];
            float4 t = t4[j];
            pn = fmaf(p.x, p.x, pn); pn = fmaf(p.y, p.y, pn);
            pn = fmaf(p.z, p.z, pn); pn = fmaf(p.w, p.w, pn);
            tn = fmaf(t.x, t.x, tn); tn = fmaf(t.y, t.y, tn);
            tn = fmaf(t.z, t.z, tn); tn = fmaf(t.w, t.w, tn);
            float dx = p.x - t.x, dy = p.y - t.y, dz = p.z - t.z, dw = p.w - t.w;
            sq = fmaf(dx, dx, sq); sq = fmaf(dy, dy, sq);
            sq = fmaf(dz, dz, sq); sq = fmaf(dw, dw, sq);
        }
        pn += __shfl_xor_sync(0xFFFFFFFFu, pn, 1);
        pn += __shfl_xor_sync(0xFFFFFFFFu, pn, 2);
        pn += __shfl_xor_sync(0xFFFFFFFFu, pn, 4);
        tn += __shfl_xor_sync(0xFFFFFFFFu, tn, 1);
        tn += __shfl_xor_sync(0xFFFFFFFFu, tn, 2);
        tn += __shfl_xor_sync(0xFFFFFFFFu, tn, 4);
        sq += __shfl_xor_sync(0xFFFFFFFFu, sq, 1);
        sq += __shfl_xor_sync(0xFFFFFFFFu, sq, 2);
        sq += __shfl_xor_sync(0xFFFFFFFFu, sq, 4);
        if (lane == 0) {
            pn = fminf(fmaxf(pn, 0.f), 1.0f - BEPS);
            tn = fminf(fmaxf(tn, 0.f), 1.0f - BEPS);
            float x = 1.0f + 2.0f * sq / ((1.0f - pn) * (1.0f - tn));
            x = fmaxf(x, 1.0f + AEPS);
            float d2c = logf(x + sqrtf(x * x - 1.0f));
            g_pn[r]    = pn;
            g_cb[r]    = 2.0f / (1.0f - pn);
            g_scorr[r] = d2c + MARGIN;
        }
    }
}

// ---------------- main: 128x128 tile, 256 threads, 8x8 micro (4+4 split) ----------------
#define BM 128
#define BN 128
#define KC 32      // k-chunk resident in smem

__device__ __forceinline__ unsigned long long pack_dup(float v) {
    unsigned long long r;
    asm("mov.b64 %0, {%1, %1};" : "=l"(r) : "f"(v));
    return r;
}
__device__ __forceinline__ void ffma2(unsigned long long& d, unsigned long long a,
                                      unsigned long long b) {
    asm("fma.rn.f32x2 %0, %1, %2, %0;" : "+l"(d) : "l"(a), "l"(b));
}
__device__ __forceinline__ void unpack2(unsigned long long v, float& lo, float& hi) {
    asm("mov.b64 {%0, %1}, %2;" : "=f"(lo), "=f"(hi) : "l"(v));
}

__global__ __launch_bounds__(256)
void poincare_main_kernel(const float* __restrict__ pred,
                          const float* __restrict__ all,
                          int B, int C) {
    // [k][m] layout, 128 floats per k-row, XOR quad swizzle: phys_quad = quad ^ (k>>2 & 7)
    __shared__ float As[KC * 128];
    __shared__ float Bs[KC * 128];
    __shared__ float red[8];

    const int tid = threadIdx.x;
    const int bm  = blockIdx.y * BM;
    const int bn  = blockIdx.x * BN;

    const int tx = tid & 15;   // n
    const int ty = tid >> 4;   // m

    unsigned long long acc2[8][4] = {};   // [a-float][col-pair]

    const float4*     As4 = (const float4*)As;
    const ulonglong2* Bs2 = (const ulonglong2*)Bs;

    for (int ch = 0; ch < 64 / KC; ch++) {
        if (ch) __syncthreads();
        // Load chunk: 128 rows x 8 float4 per tile; 4 float4 per thread per tile.
#pragma unroll
        for (int i = 0; i < 4; i++) {
            int idx = tid + i * 256;      // 0..1023
            int row = idx >> 3;           // 0..127
            int kq  = idx & 7;            // float4 index within chunk
            // swizzled scalar column (same for the 4 scalars of this float4)
            int col = (((row >> 2) ^ kq) << 2) | (row & 3);
            int kb  = (kq << 2) * 128;

            float4 v = make_float4(0.f, 0.f, 0.f, 0.f);
            int m = bm + row;
            if (m < B) v = ((const float4*)pred)[(size_t)m * 16 + ch * 8 + kq];
            As[kb       + col] = v.x;
            As[kb + 128 + col] = v.y;
            As[kb + 256 + col] = v.z;
            As[kb + 384 + col] = v.w;

            float4 w = make_float4(0.f, 0.f, 0.f, 0.f);
            int c = bn + row;
            if (c < C) w = ((const float4*)all)[(size_t)c * 16 + ch * 8 + kq];
            Bs[kb       + col] = w.x;
            Bs[kb + 128 + col] = w.y;
            Bs[kb + 256 + col] = w.z;
            Bs[kb + 384 + col] = w.w;
        }
        __syncthreads();

#pragma unroll 4
        for (int k = 0; k < KC; k++) {
            int sw = (k >> 2) & 7;
            int qa = ty ^ sw;
            int qb = tx ^ sw;
            float4     a_lo = As4[k * 32 + qa];
            float4     a_hi = As4[k * 32 + 16 + qa];
            ulonglong2 b_lo = Bs2[k * 32 + qb];        // cols tx*4+0..3
            ulonglong2 b_hi = Bs2[k * 32 + 16 + qb];   // cols 64+tx*4+0..3

            unsigned long long a0 = pack_dup(a_lo.x);
            unsigned long long a1 = pack_dup(a_lo.y);
            unsigned long long a2 = pack_dup(a_lo.z);
            unsigned long long a3 = pack_dup(a_lo.w);
            unsigned long long a4 = pack_dup(a_hi.x);
            unsigned long long a5 = pack_dup(a_hi.y);
            unsigned long long a6 = pack_dup(a_hi.z);
            unsigned long long a7 = pack_dup(a_hi.w);

            ffma2(acc2[0][0], a0, b_lo.x); ffma2(acc2[0][1], a0, b_lo.y);
            ffma2(acc2[0][2], a0, b_hi.x); ffma2(acc2[0][3], a0, b_hi.y);
            ffma2(acc2[1][0], a1, b_lo.x); ffma2(acc2[1][1], a1, b_lo.y);
            ffma2(acc2[1][2], a1, b_hi.x); ffma2(acc2[1][3], a1, b_hi.y);
            ffma2(acc2[2][0], a2, b_lo.x); ffma2(acc2[2][1], a2, b_lo.y);
            ffma2(acc2[2][2], a2, b_hi.x); ffma2(acc2[2][3], a2, b_hi.y);
            ffma2(acc2[3][0], a3, b_lo.x); ffma2(acc2[3][1], a3, b_lo.y);
            ffma2(acc2[3][2], a3, b_hi.x); ffma2(acc2[3][3], a3, b_hi.y);
            ffma2(acc2[4][0], a4, b_lo.x); ffma2(acc2[4][1], a4, b_lo.y);
            ffma2(acc2[4][2], a4, b_hi.x); ffma2(acc2[4][3], a4, b_hi.y);
            ffma2(acc2[5][0], a5, b_lo.x); ffma2(acc2[5][1], a5, b_lo.y);
            ffma2(acc2[5][2], a5, b_hi.x); ffma2(acc2[5][3], a5, b_hi.y);
            ffma2(acc2[6][0], a6, b_lo.x); ffma2(acc2[6][1], a6, b_lo.y);
            ffma2(acc2[6][2], a6, b_hi.x); ffma2(acc2[6][3], a6, b_hi.y);
            ffma2(acc2[7][0], a7, b_lo.x); ffma2(acc2[7][1], a7, b_lo.y);
            ffma2(acc2[7][2], a7, b_hi.x); ffma2(acc2[7][3], a7, b_hi.y);
        }
    }

    // Row / col epilogue params. Rows: bm + ty*4 + i (i<4), bm + 64 + ty*4 + (i-4).
    float pnv[8], cbv[8], scv[8];
    bool  mv[8];
#pragma unroll
    for (int i = 0; i < 8; i++) {
        int m = bm + ((i < 4) ? (ty * 4 + i) : (64 + ty * 4 + i - 4));
        mv[i] = (m < B);
        int mc = mv[i] ? m : 0;
        pnv[i] = g_pn[mc];
        cbv[i] = g_cb[mc];
        scv[i] = g_scorr[mc];
    }
    float anv[8], cav[8];
    bool  cv[8];
#pragma unroll
    for (int j = 0; j < 8; j++) {
        int c = bn + ((j < 4) ? (tx * 4 + j) : (64 + tx * 4 + j - 4));
        cv[j] = (c < C);
        int cc = cv[j] ? c : 0;
        anv[j] = g_an[cc];
        cav[j] = g_ca[cc];
    }

    float acc_h = 0.f;
#pragma unroll
    for (int i = 0; i < 8; i++) {
        float acc[8];
        unpack2(acc2[i][0], acc[0], acc[1]);
        unpack2(acc2[i][1], acc[2], acc[3]);
        unpack2(acc2[i][2], acc[4], acc[5]);
        unpack2(acc2[i][3], acc[6], acc[7]);
#pragma unroll
        for (int j = 0; j < 8; j++) {
            if (mv[i] && cv[j]) {
                float sqd = fmaxf(pnv[i] + anv[j] - 2.0f * acc[j], 0.f);
                float x   = fmaf(sqd, cbv[i] * cav[j], 1.0f);
                x = fmaxf(x, 1.0f + AEPS);
                float d = __logf(x + __fsqrt_rn(fmaf(x, x, -1.0f)));
                acc_h += fmaxf(scv[i] - d, 0.f);
            }
        }
    }

    // warp reduce + cross-warp reduce
#pragma unroll
    for (int s = 16; s > 0; s >>= 1)
        acc_h += __shfl_xor_sync(0xFFFFFFFFu, acc_h, s);
    int wid = tid >> 5, lid = tid & 31;
    if (lid == 0) red[wid] = acc_h;
    __syncthreads();
    if (wid == 0) {
        float v = (lid < 8) ? red[lid] : 0.f;
#pragma unroll
        for (int s = 4; s > 0; s >>= 1)
            v += __shfl_xor_sync(0xFFFFFFFFu, v, s);
        if (lid == 0) atomicAdd(&g_hsum, (double)v);
    }
}

__global__ void finalize_kernel(float* out, int B) {
    double h = g_hsum;
    out[0] = (float)((h - 0.1 * (double)B) / (double)B);
}

extern "C" void kernel_launch(void* const* d_in, const int* in_sizes, int n_in,
                              void* d_out, int out_size) {
    const float* pred = (const float*)d_in[0];
    const float* tgt  = (const float*)d_in[1];
    const float* all  = (const float*)d_in[2];
    float* out = (float*)d_out;

    int B = in_sizes[0] / 64;
    int C = in_sizes[2] / 64;

    int nthr = ((B > C) ? B : C) * 8;
    prep_kernel<<<(nthr + 255) / 256, 256>>>(pred, tgt, all, B, C);

    dim3 grid((C + BN - 1) / BN, (B + BM - 1) / BM);
    poincare_main_kernel<<<grid, 256>>>(pred, all, B, C);

    finalize_kernel<<<1, 1>>>(out, B);
}

// round 5
// speedup vs baseline: 1.8567x; 1.8567x over previous
#include <cuda_runtime.h>
#include <cuda_bf16.h>
#include <cstdint>

#define MARGIN   0.1f
#define BEPS     1e-5f
#define AEPS     1e-7f
#define LN2      0.69314718056f

#define MAXB 4608
#define MAXC 10240

static __device__ double g_hsum;
static __device__ float4 g_rowp[MAXB];   // (pn, 2/(1-pn), dist2correct+MARGIN, 0)
static __device__ float2 g_colp[MAXC];   // (an, 1/(1-an))

// ---------------- helpers ----------------
__device__ __forceinline__ uint32_t smem_u32(const void* p) {
    uint32_t a;
    asm("{ .reg .u64 t; cvta.to.shared.u64 t, %1; cvt.u32.u64 %0, t; }" : "=r"(a) : "l"(p));
    return a;
}
__device__ __forceinline__ uint32_t f2tf32(float v) {
    uint32_t r;
    asm("cvt.rna.tf32.f32 %0, %1;" : "=r"(r) : "f"(v));
    return r;
}
__device__ __forceinline__ void ldm_x4(uint32_t* r, uint32_t addr) {
    asm volatile("ldmatrix.sync.aligned.m8n8.x4.shared.b16 {%0,%1,%2,%3}, [%4];"
                 : "=r"(r[0]), "=r"(r[1]), "=r"(r[2]), "=r"(r[3]) : "r"(addr));
}
__device__ __forceinline__ void mma_tf32(float* c, const uint32_t* a,
                                         uint32_t b0, uint32_t b1) {
    asm volatile(
        "mma.sync.aligned.m16n8k8.row.col.f32.tf32.tf32.f32 "
        "{%0,%1,%2,%3}, {%4,%5,%6,%7}, {%8,%9}, {%0,%1,%2,%3};"
        : "+f"(c[0]), "+f"(c[1]), "+f"(c[2]), "+f"(c[3])
        : "r"(a[0]), "r"(a[1]), "r"(a[2]), "r"(a[3]), "r"(b0), "r"(b1));
}

// ---------------- prep ----------------
__global__ void prep_kernel(const float* __restrict__ pred,
                            const float* __restrict__ tgt,
                            const float* __restrict__ all,
                            int B, int C) {
    int gid  = blockIdx.x * blockDim.x + threadIdx.x;
    int r    = gid >> 3;
    int lane = gid & 7;
    if (gid == 0) g_hsum = 0.0;

    if (r < C) {
        const float4* a4 = (const float4*)(all + (size_t)r * 64) + lane * 2;
        float s = 0.f;
#pragma unroll
        for (int j = 0; j < 2; j++) {
            float4 v = a4[j];
            s = fmaf(v.x, v.x, s); s = fmaf(v.y, v.y, s);
            s = fmaf(v.z, v.z, s); s = fmaf(v.w, v.w, s);
        }
        s += __shfl_xor_sync(0xFFFFFFFFu, s, 1);
        s += __shfl_xor_sync(0xFFFFFFFFu, s, 2);
        s += __shfl_xor_sync(0xFFFFFFFFu, s, 4);
        if (lane == 0) {
            s = fminf(fmaxf(s, 0.f), 1.0f - BEPS);
            g_colp[r] = make_float2(s, 1.0f / (1.0f - s));
        }
    }

    if (r < B) {
        const float4* p4 = (const float4*)(pred + (size_t)r * 64) + lane * 2;
        const float4* t4 = (const float4*)(tgt  + (size_t)r * 64) + lane * 2;
        float pn = 0.f, tn = 0.f, sq = 0.f;
#pragma unroll
        for (int j = 0; j < 2; j++) {
            float4 p = p4[j];
            float4 t = t4[j];
            pn = fmaf(p.x, p.x, pn); pn = fmaf(p.y, p.y, pn);
            pn = fmaf(p.z, p.z, pn); pn = fmaf(p.w, p.w, pn);
            tn = fmaf(t.x, t.x, tn); tn = fmaf(t.y, t.y, tn);
            tn = fmaf(t.z, t.z, tn); tn = fmaf(t.w, t.w, tn);
            float dx = p.x - t.x, dy = p.y - t.y, dz = p.z - t.z, dw = p.w - t.w;
            sq = fmaf(dx, dx, sq); sq = fmaf(dy, dy, sq);
            sq = fmaf(dz, dz, sq); sq = fmaf(dw, dw, sq);
        }
        pn += __shfl_xor_sync(0xFFFFFFFFu, pn, 1);
        pn += __shfl_xor_sync(0xFFFFFFFFu, pn, 2);
        pn += __shfl_xor_sync(0xFFFFFFFFu, pn, 4);
        tn += __shfl_xor_sync(0xFFFFFFFFu, tn, 1);
        tn += __shfl_xor_sync(0xFFFFFFFFu, tn, 2);
        tn += __shfl_xor_sync(0xFFFFFFFFu, tn, 4);
        sq += __shfl_xor_sync(0xFFFFFFFFu, sq, 1);
        sq += __shfl_xor_sync(0xFFFFFFFFu, sq, 2);
        sq += __shfl_xor_sync(0xFFFFFFFFu, sq, 4);
        if (lane == 0) {
            pn = fminf(fmaxf(pn, 0.f), 1.0f - BEPS);
            tn = fminf(fmaxf(tn, 0.f), 1.0f - BEPS);
            float x = 1.0f + 2.0f * sq / ((1.0f - pn) * (1.0f - tn));
            x = fmaxf(x, 1.0f + AEPS);
            float d2c = logf(x + sqrtf(x * x - 1.0f));
            g_rowp[r] = make_float4(pn, 2.0f / (1.0f - pn), d2c + MARGIN, 0.f);
        }
    }
}

// ---------------- main: mma.sync tf32, 128x128 per CTA ----------------
#define BM 128
#define BN 128

// dynamic smem layout
#define OFF_A    0        // 32768 B (128 rows x 256 B, K-major, quad-XOR swizzle)
#define OFF_B    32768    // 32768 B
#define OFF_CP   65536    // float2[128] = 1024 B
#define OFF_RED  66560    // float[8]
#define SMEM_SZ  66624

__global__ __launch_bounds__(256, 2)
void poincare_mma_kernel(const float* __restrict__ pred,
                         const float* __restrict__ all,
                         int B, int C) {
    extern __shared__ char smem[];
    const uint32_t sbase = smem_u32(smem);
    const int tid  = threadIdx.x;
    const int w    = tid >> 5;
    const int lane = tid & 31;
    const int bm   = blockIdx.y * BM;
    const int bn   = blockIdx.x * BN;
    const int wm   = w & 3;    // m-block (32 rows)
    const int wn   = w >> 2;   // n-block (64 cols)

    // ---- load tiles (tf32-converted, swizzled K-major) ----
#pragma unroll
    for (int i = 0; i < 8; i++) {
        int idx = tid + i * 256;          // 0..2047
        int r   = idx >> 4;               // 0..127
        int kq  = idx & 15;               // float4 along k
        uint32_t so = (uint32_t)(r * 256) + (uint32_t)(((kq ^ (r & 7)) << 4));

        float4 v = make_float4(0.f, 0.f, 0.f, 0.f);
        int m = bm + r;
        if (m < B) v = ((const float4*)pred)[(size_t)m * 16 + kq];
        *(uint4*)(smem + OFF_A + so) =
            make_uint4(f2tf32(v.x), f2tf32(v.y), f2tf32(v.z), f2tf32(v.w));

        float4 u = make_float4(0.f, 0.f, 0.f, 0.f);
        int c = bn + r;
        if (c < C) u = ((const float4*)all)[(size_t)c * 16 + kq];
        *(uint4*)(smem + OFF_B + so) =
            make_uint4(f2tf32(u.x), f2tf32(u.y), f2tf32(u.z), f2tf32(u.w));
    }
    if (tid < 128) {
        int c = bn + tid;
        float2 cp = (c < C) ? g_colp[c] : make_float2(0.f, 1.f);
        ((float2*)(smem + OFF_CP))[tid] = cp;
    }
    __syncthreads();

    // ---- fragment addresses ----
    // A: row = wm*32 + i*16 + (lane&15); kq = 2s + (lane>>4)
    const int rA  = wm * 32 + (lane & 15);
    const int kA  = lane >> 4;
    const int swA = rA & 7;
    const uint32_t baseA = sbase + OFF_A + (uint32_t)(rA * 256);
    // B: row = wn*64 + jp*16 + (lane&7) + ((lane>>4)<<3); kq = 2s + ((lane>>3)&1)
    const int rB  = wn * 64 + (lane & 7) + ((lane >> 4) << 3);
    const int kB  = (lane >> 3) & 1;
    const int swB = rB & 7;
    const uint32_t baseB = sbase + OFF_B + (uint32_t)(rB * 256);

    float acc[2][8][4];
#pragma unroll
    for (int i = 0; i < 2; i++)
#pragma unroll
        for (int j = 0; j < 8; j++)
#pragma unroll
            for (int q = 0; q < 4; q++) acc[i][j][q] = 0.f;

#pragma unroll
    for (int s = 0; s < 8; s++) {
        uint32_t af[2][4];
#pragma unroll
        for (int i = 0; i < 2; i++)
            ldm_x4(af[i], baseA + (uint32_t)(i * 16 * 256)
                        + (uint32_t)((((2 * s + kA) ^ swA) << 4)));
        uint32_t bf[4][4];
#pragma unroll
        for (int jp = 0; jp < 4; jp++)
            ldm_x4(bf[jp], baseB + (uint32_t)(jp * 16 * 256)
                         + (uint32_t)((((2 * s + kB) ^ swB) << 4)));
#pragma unroll
        for (int i = 0; i < 2; i++) {
#pragma unroll
            for (int jp = 0; jp < 4; jp++) {
                mma_tf32(acc[i][jp * 2],     af[i], bf[jp][0], bf[jp][1]);
                mma_tf32(acc[i][jp * 2 + 1], af[i], bf[jp][2], bf[jp][3]);
            }
        }
    }

    // ---- epilogue ----
    // element (i,j,q): row = bm + wm*32 + i*16 + lane/4 + 8*(q>>1)
    //                  col = bn + wn*64 + j*8 + 2*(lane&3) + (q&1)
    float4 rp[4];
    bool   mv[4];
#pragma unroll
    for (int t = 0; t < 4; t++) {
        int m = bm + wm * 32 + (lane >> 2) + t * 8;   // t = 2*i + (q>>1)
        mv[t] = (m < B);
        rp[t] = mv[t] ? g_rowp[m] : make_float4(0.f, 2.f, 0.f, 0.f);
    }

    float hs = 0.f;
#pragma unroll
    for (int j = 0; j < 8; j++) {
        int cbase = wn * 64 + j * 8 + 2 * (lane & 3);
        float4 cp2 = *(const float4*)(smem + OFF_CP + (uint32_t)(cbase << 3));
        // cp2 = (an0, ca0, an1, ca1)
        bool cv0 = (bn + cbase) < C;
        bool cv1 = (bn + cbase + 1) < C;
#pragma unroll
        for (int i = 0; i < 2; i++) {
#pragma unroll
            for (int h = 0; h < 2; h++) {        // h = q>>1 (row half)
                int t = 2 * i + h;
                if (!mv[t]) continue;
                float4 r4 = rp[t];
#pragma unroll
                for (int q = 0; q < 2; q++) {    // q = col parity
                    if (q == 0 ? !cv0 : !cv1) continue;
                    float an = q == 0 ? cp2.x : cp2.z;
                    float ca = q == 0 ? cp2.y : cp2.w;
                    float dot = acc[i][j][h * 2 + q];
                    float sqd = fmaxf(fmaf(-2.f, dot, r4.x + an), 0.f);
                    float x   = fmaf(sqd, r4.y * ca, 1.0f);
                    x = fmaxf(x, 1.0f + AEPS);
                    float tq = fmaf(x, x, -1.0f);
                    float st;  asm("sqrt.approx.f32 %0, %1;" : "=f"(st) : "f"(tq));
                    float arg = x + st;
                    float lg;  asm("lg2.approx.f32 %0, %1;" : "=f"(lg) : "f"(arg));
                    hs += fmaxf(fmaf(-LN2, lg, r4.z), 0.f);
                }
            }
        }
    }

    // ---- reduce ----
#pragma unroll
    for (int s = 16; s > 0; s >>= 1)
        hs += __shfl_xor_sync(0xFFFFFFFFu, hs, s);
    if (lane == 0) ((float*)(smem + OFF_RED))[w] = hs;
    __syncthreads();
    if (w == 0) {
        float v = (lane < 8) ? ((float*)(smem + OFF_RED))[lane] : 0.f;
#pragma unroll
        for (int s = 4; s > 0; s >>= 1)
            v += __shfl_xor_sync(0xFFFFFFFFu, v, s);
        if (lane == 0) atomicAdd(&g_hsum, (double)v);
    }
}

__global__ void finalize_kernel(float* out, int B) {
    double h = g_hsum;
    out[0] = (float)((h - 0.1 * (double)B) / (double)B);
}

extern "C" void kernel_launch(void* const* d_in, const int* in_sizes, int n_in,
                              void* d_out, int out_size) {
    const float* pred = (const float*)d_in[0];
    const float* tgt  = (const float*)d_in[1];
    const float* all  = (const float*)d_in[2];
    float* out = (float*)d_out;

    int B = in_sizes[0] / 64;
    int C = in_sizes[2] / 64;

    cudaFuncSetAttribute(poincare_mma_kernel,
                         cudaFuncAttributeMaxDynamicSharedMemorySize, SMEM_SZ);

    int nthr = ((B > C) ? B : C) * 8;
    prep_kernel<<<(nthr + 255) / 256, 256>>>(pred, tgt, all, B, C);

    dim3 grid((C + BN - 1) / BN, (B + BM - 1) / BM);
    poincare_mma_kernel<<<grid, 256, SMEM_SZ>>>(pred, all, B, C);

    finalize_kernel<<<1, 1>>>(out, B);
}

// round 6
// speedup vs baseline: 2.8270x; 1.5226x over previous
#include <cuda_runtime.h>
#include <cuda_bf16.h>
#include <cstdint>

#define MARGIN   0.1f
#define BEPS     1e-5f
#define AEPS     1e-7f
#define LN2      0.69314718056f
#define INV_LN2  1.44269504089f

#define MAXB 4608
#define MAXC 10240

static __device__ double   g_hsum;
static __device__ float4   g_rowp[MAXB];          // (pn*cb, cb, sc2, 0)
static __device__ float2   g_colp[MAXC];          // (ca, an*ca)  [pad: (0, 1e18)]
static __device__ uint32_t g_As[MAXB * 64];       // tf32(-2*cb*pred), row-swizzled
static __device__ uint32_t g_Bs[MAXC * 64];       // tf32(ca*all),     row-swizzled

// ---------------- helpers ----------------
__device__ __forceinline__ uint32_t smem_u32(const void* p) {
    uint32_t a;
    asm("{ .reg .u64 t; cvta.to.shared.u64 t, %1; cvt.u32.u64 %0, t; }" : "=r"(a) : "l"(p));
    return a;
}
__device__ __forceinline__ uint32_t f2tf32(float v) {
    uint32_t r;
    asm("cvt.rna.tf32.f32 %0, %1;" : "=r"(r) : "f"(v));
    return r;
}
__device__ __forceinline__ void ldm_x4(uint32_t* r, uint32_t addr) {
    asm volatile("ldmatrix.sync.aligned.m8n8.x4.shared.b16 {%0,%1,%2,%3}, [%4];"
                 : "=r"(r[0]), "=r"(r[1]), "=r"(r[2]), "=r"(r[3]) : "r"(addr));
}
__device__ __forceinline__ void mma_tf32(float* c, const uint32_t* a,
                                         uint32_t b0, uint32_t b1) {
    asm volatile(
        "mma.sync.aligned.m16n8k8.row.col.f32.tf32.tf32.f32 "
        "{%0,%1,%2,%3}, {%4,%5,%6,%7}, {%8,%9}, {%0,%1,%2,%3};"
        : "+f"(c[0]), "+f"(c[1]), "+f"(c[2]), "+f"(c[3])
        : "r"(a[0]), "r"(a[1]), "r"(a[2]), "r"(a[3]), "r"(b0), "r"(b1));
}
__device__ __forceinline__ void cp_async16(uint32_t smem_addr, const void* gmem) {
    asm volatile("cp.async.cg.shared.global [%0], [%1], 16;"
                 :: "r"(smem_addr), "l"(gmem) : "memory");
}

// ---------------- prep: scale, convert, swizzle ----------------
__global__ void prep_kernel(const float* __restrict__ pred,
                            const float* __restrict__ tgt,
                            const float* __restrict__ all,
                            int B, int C, int Bp, int Cp) {
    int gid  = blockIdx.x * blockDim.x + threadIdx.x;
    int r    = gid >> 3;
    int lane = gid & 7;
    if (gid == 0) g_hsum = 0.0;

    // ---- columns (all_embs) ----
    if (r < Cp) {
        if (r < C) {
            float4 a0 = ((const float4*)(all + (size_t)r * 64))[lane * 2];
            float4 a1 = ((const float4*)(all + (size_t)r * 64))[lane * 2 + 1];
            float s = 0.f;
            s = fmaf(a0.x, a0.x, s); s = fmaf(a0.y, a0.y, s);
            s = fmaf(a0.z, a0.z, s); s = fmaf(a0.w, a0.w, s);
            s = fmaf(a1.x, a1.x, s); s = fmaf(a1.y, a1.y, s);
            s = fmaf(a1.z, a1.z, s); s = fmaf(a1.w, a1.w, s);
            s += __shfl_xor_sync(0xFFFFFFFFu, s, 1);
            s += __shfl_xor_sync(0xFFFFFFFFu, s, 2);
            s += __shfl_xor_sync(0xFFFFFFFFu, s, 4);
            float an = fminf(fmaxf(s, 0.f), 1.0f - BEPS);
            float ca = 1.0f / (1.0f - an);
            // scaled tf32, swizzled store
            int kq0 = lane * 2, kq1 = lane * 2 + 1;
            uint32_t* dst = g_Bs + (size_t)r * 64;
            *(uint4*)(dst + ((kq0 ^ (r & 7)) << 2)) =
                make_uint4(f2tf32(ca*a0.x), f2tf32(ca*a0.y), f2tf32(ca*a0.z), f2tf32(ca*a0.w));
            *(uint4*)(dst + ((kq1 ^ (r & 7)) << 2)) =
                make_uint4(f2tf32(ca*a1.x), f2tf32(ca*a1.y), f2tf32(ca*a1.z), f2tf32(ca*a1.w));
            if (lane == 0) g_colp[r] = make_float2(ca, an * ca);
        } else {
            uint32_t* dst = g_Bs + (size_t)r * 64 + lane * 8;
            *(uint4*)(dst)     = make_uint4(0u, 0u, 0u, 0u);
            *(uint4*)(dst + 4) = make_uint4(0u, 0u, 0u, 0u);
            if (lane == 0) g_colp[r] = make_float2(0.f, 1e18f);
        }
    }

    // ---- rows (pred / target) ----
    if (r < Bp) {
        if (r < B) {
            float4 p0 = ((const float4*)(pred + (size_t)r * 64))[lane * 2];
            float4 p1 = ((const float4*)(pred + (size_t)r * 64))[lane * 2 + 1];
            float4 t0 = ((const float4*)(tgt  + (size_t)r * 64))[lane * 2];
            float4 t1 = ((const float4*)(tgt  + (size_t)r * 64))[lane * 2 + 1];
            float pn = 0.f, tn = 0.f, sq = 0.f;
            pn = fmaf(p0.x,p0.x,pn); pn = fmaf(p0.y,p0.y,pn); pn = fmaf(p0.z,p0.z,pn); pn = fmaf(p0.w,p0.w,pn);
            pn = fmaf(p1.x,p1.x,pn); pn = fmaf(p1.y,p1.y,pn); pn = fmaf(p1.z,p1.z,pn); pn = fmaf(p1.w,p1.w,pn);
            tn = fmaf(t0.x,t0.x,tn); tn = fmaf(t0.y,t0.y,tn); tn = fmaf(t0.z,t0.z,tn); tn = fmaf(t0.w,t0.w,tn);
            tn = fmaf(t1.x,t1.x,tn); tn = fmaf(t1.y,t1.y,tn); tn = fmaf(t1.z,t1.z,tn); tn = fmaf(t1.w,t1.w,tn);
            float dx;
            dx = p0.x-t0.x; sq = fmaf(dx,dx,sq); dx = p0.y-t0.y; sq = fmaf(dx,dx,sq);
            dx = p0.z-t0.z; sq = fmaf(dx,dx,sq); dx = p0.w-t0.w; sq = fmaf(dx,dx,sq);
            dx = p1.x-t1.x; sq = fmaf(dx,dx,sq); dx = p1.y-t1.y; sq = fmaf(dx,dx,sq);
            dx = p1.z-t1.z; sq = fmaf(dx,dx,sq); dx = p1.w-t1.w; sq = fmaf(dx,dx,sq);
            pn += __shfl_xor_sync(0xFFFFFFFFu, pn, 1);
            pn += __shfl_xor_sync(0xFFFFFFFFu, pn, 2);
            pn += __shfl_xor_sync(0xFFFFFFFFu, pn, 4);
            tn += __shfl_xor_sync(0xFFFFFFFFu, tn, 1);
            tn += __shfl_xor_sync(0xFFFFFFFFu, tn, 2);
            tn += __shfl_xor_sync(0xFFFFFFFFu, tn, 4);
            sq += __shfl_xor_sync(0xFFFFFFFFu, sq, 1);
            sq += __shfl_xor_sync(0xFFFFFFFFu, sq, 2);
            sq += __shfl_xor_sync(0xFFFFFFFFu, sq, 4);
            pn = fminf(fmaxf(pn, 0.f), 1.0f - BEPS);
            tn = fminf(fmaxf(tn, 0.f), 1.0f - BEPS);
            float cb = 2.0f / (1.0f - pn);
            float m2cb = -2.0f * cb;
            int kq0 = lane * 2, kq1 = lane * 2 + 1;
            uint32_t* dst = g_As + (size_t)r * 64;
            *(uint4*)(dst + ((kq0 ^ (r & 7)) << 2)) =
                make_uint4(f2tf32(m2cb*p0.x), f2tf32(m2cb*p0.y), f2tf32(m2cb*p0.z), f2tf32(m2cb*p0.w));
            *(uint4*)(dst + ((kq1 ^ (r & 7)) << 2)) =
                make_uint4(f2tf32(m2cb*p1.x), f2tf32(m2cb*p1.y), f2tf32(m2cb*p1.z), f2tf32(m2cb*p1.w));
            if (lane == 0) {
                float x = 1.0f + 2.0f * sq / ((1.0f - pn) * (1.0f - tn));
                x = fmaxf(x, 1.0f + AEPS);
                float d2c = logf(x + sqrtf(x * x - 1.0f));
                g_rowp[r] = make_float4(pn * cb, cb, (d2c + MARGIN) * INV_LN2, 0.f);
            }
        } else {
            uint32_t* dst = g_As + (size_t)r * 64 + lane * 8;
            *(uint4*)(dst)     = make_uint4(0u, 0u, 0u, 0u);
            *(uint4*)(dst + 4) = make_uint4(0u, 0u, 0u, 0u);
            if (lane == 0) g_rowp[r] = make_float4(0.f, 0.f, 0.f, 0.f);
        }
    }
}

// ---------------- main: mma.sync tf32 + folded extras ----------------
#define BM 128
#define BN 128
#define OFF_A    0        // 32768 B
#define OFF_B    32768    // 32768 B
#define OFF_CP   65536    // float2[128]
#define OFF_RED  66560    // float[8]
#define SMEM_SZ  66624

__global__ __launch_bounds__(256, 2)
void poincare_mma_kernel(int B, int C) {
    extern __shared__ char smem[];
    const uint32_t sbase = smem_u32(smem);
    const int tid  = threadIdx.x;
    const int w    = tid >> 5;
    const int lane = tid & 31;
    const int bm   = blockIdx.y * BM;
    const int bn   = blockIdx.x * BN;
    const int wm   = w & 3;
    const int wn   = w >> 2;

    // ---- async tile copy (swizzle baked in gmem -> plain linear copy) ----
    {
        const uint32_t* srcA = g_As + (size_t)bm * 64;
        const uint32_t* srcB = g_Bs + (size_t)bn * 64;
#pragma unroll
        for (int i = 0; i < 8; i++) {
            int idx = tid + i * 256;                 // float4 index 0..2047
            cp_async16(sbase + OFF_A + (idx << 4), srcA + (idx << 2));
            cp_async16(sbase + OFF_B + (idx << 4), srcB + (idx << 2));
        }
        asm volatile("cp.async.commit_group;" ::: "memory");
    }
    // stage column params
    if (tid < 128) {
        float2 cpv = g_colp[bn + tid];
        ((float2*)(smem + OFF_CP))[tid] = cpv;
    }
    asm volatile("cp.async.wait_group 0;" ::: "memory");
    __syncthreads();

    // ---- fragment addressing (as R4) ----
    const int rA  = wm * 32 + (lane & 15);
    const int kA  = lane >> 4;
    const int swA = rA & 7;
    const uint32_t baseA = sbase + OFF_A + (uint32_t)(rA * 256);
    const int rB  = wn * 64 + (lane & 7) + ((lane >> 4) << 3);
    const int kB  = (lane >> 3) & 1;
    const int swB = rB & 7;
    const uint32_t baseB = sbase + OFF_B + (uint32_t)(rB * 256);

    float acc[2][8][4];
#pragma unroll
    for (int i = 0; i < 2; i++)
#pragma unroll
        for (int j = 0; j < 8; j++)
#pragma unroll
            for (int q = 0; q < 4; q++) acc[i][j][q] = 0.f;

#pragma unroll
    for (int s = 0; s < 8; s++) {
        uint32_t af[2][4];
#pragma unroll
        for (int i = 0; i < 2; i++)
            ldm_x4(af[i], baseA + (uint32_t)(i * 16 * 256)
                        + (uint32_t)((((2 * s + kA) ^ swA) << 4)));
        uint32_t bf[4][4];
#pragma unroll
        for (int jp = 0; jp < 4; jp++)
            ldm_x4(bf[jp], baseB + (uint32_t)(jp * 16 * 256)
                         + (uint32_t)((((2 * s + kB) ^ swB) << 4)));
#pragma unroll
        for (int i = 0; i < 2; i++) {
#pragma unroll
            for (int jp = 0; jp < 4; jp++) {
                mma_tf32(acc[i][jp * 2],     af[i], bf[jp][0], bf[jp][1]);
                mma_tf32(acc[i][jp * 2 + 1], af[i], bf[jp][2], bf[jp][3]);
            }
        }
    }

    // ---- extras k-step: adds cb*ca*(pn+an) so acc = cbca*(pn+an-2*dot) ----
    // Row params for rows r = bm + wm*32 + (lane>>2) + 8*t  (t = 2i+h)
    float4 rp[4];
#pragma unroll
    for (int t = 0; t < 4; t++)
        rp[t] = g_rowp[bm + wm * 32 + (lane >> 2) + t * 8];

    {
        const int ksel = lane & 3;
        const float2* cp = (const float2*)(smem + OFF_CP);
        uint32_t aex[2][4];
#pragma unroll
        for (int i = 0; i < 2; i++) {
            float a0 = (ksel == 0) ? rp[2 * i].x : (ksel == 1) ? rp[2 * i].y : 0.f;
            float a1 = (ksel == 0) ? rp[2 * i + 1].x : (ksel == 1) ? rp[2 * i + 1].y : 0.f;
            aex[i][0] = f2tf32(a0);
            aex[i][1] = f2tf32(a1);
            aex[i][2] = 0u;
            aex[i][3] = 0u;
        }
        uint32_t bex[8];
#pragma unroll
        for (int jn = 0; jn < 8; jn++) {
            float2 cc = cp[wn * 64 + jn * 8 + (lane >> 2)];
            float b0 = (ksel == 0) ? cc.x : (ksel == 1) ? cc.y : 0.f;
            bex[jn] = f2tf32(b0);
        }
#pragma unroll
        for (int i = 0; i < 2; i++)
#pragma unroll
            for (int jn = 0; jn < 8; jn++)
                mma_tf32(acc[i][jn], aex[i], bex[jn], 0u);
    }

    // ---- epilogue: 5 fma-pipe ops + 2 MUFU per element ----
    float hs = 0.f;
#pragma unroll
    for (int i = 0; i < 2; i++) {
#pragma unroll
        for (int j = 0; j < 8; j++) {
#pragma unroll
            for (int h = 0; h < 2; h++) {
                float sc2 = rp[2 * i + h].z;
#pragma unroll
                for (int q = 0; q < 2; q++) {
                    float e = acc[i][j][h * 2 + q];
                    float g = fmaxf(e, 0.f);
                    float x = fmaxf(g + 1.0f, 1.0f + AEPS);
                    float tq = fmaf(x, x, -1.0f);
                    float st;  asm("sqrt.approx.f32 %0, %1;" : "=f"(st) : "f"(tq));
                    float arg = x + st;
                    float lg;  asm("lg2.approx.f32 %0, %1;" : "=f"(lg) : "f"(arg));
                    hs += fmaxf(sc2 - lg, 0.f);
                }
            }
        }
    }

    // ---- reduce (scale by LN2 once) ----
#pragma unroll
    for (int s = 16; s > 0; s >>= 1)
        hs += __shfl_xor_sync(0xFFFFFFFFu, hs, s);
    if (lane == 0) ((float*)(smem + OFF_RED))[w] = hs;
    __syncthreads();
    if (w == 0) {
        float v = (lane < 8) ? ((float*)(smem + OFF_RED))[lane] : 0.f;
#pragma unroll
        for (int s = 4; s > 0; s >>= 1)
            v += __shfl_xor_sync(0xFFFFFFFFu, v, s);
        if (lane == 0) atomicAdd(&g_hsum, (double)(v * LN2));
    }
}

__global__ void finalize_kernel(float* out, int B) {
    double h = g_hsum;
    out[0] = (float)((h - 0.1 * (double)B) / (double)B);
}

extern "C" void kernel_launch(void* const* d_in, const int* in_sizes, int n_in,
                              void* d_out, int out_size) {
    const float* pred = (const float*)d_in[0];
    const float* tgt  = (const float*)d_in[1];
    const float* all  = (const float*)d_in[2];
    float* out = (float*)d_out;

    int B = in_sizes[0] / 64;
    int C = in_sizes[2] / 64;
    int Bp = ((B + 127) / 128) * 128;   // padded (arrays sized for MAXB/MAXC)
    int Cp = ((C + 127) / 128) * 128;

    cudaFuncSetAttribute(poincare_mma_kernel,
                         cudaFuncAttributeMaxDynamicSharedMemorySize, SMEM_SZ);

    int nthr = ((Bp > Cp) ? Bp : Cp) * 8;
    prep_kernel<<<(nthr + 255) / 256, 256>>>(pred, tgt, all, B, C, Bp, Cp);

    dim3 grid(Cp / BN, Bp / BM);
    poincare_mma_kernel<<<grid, 256, SMEM_SZ>>>(B, C);

    finalize_kernel<<<1, 1>>>(out, B);
}

// round 7
// speedup vs baseline: 3.7605x; 1.3302x over previous
#include <cuda_runtime.h>
#include <cuda_fp16.h>
#include <cstdint>

#define MARGIN   0.1f
#define BEPS     1e-5f
#define LN2      0.69314718056f
#define INV_LN2  1.44269504089f

#define MAXB 4608
#define MAXC 10240

static __device__ double  g_hsum;
static __device__ float4  g_rowp[MAXB];        // (pn*cb, cb, sc2, 0)
static __device__ float2  g_colp[MAXC];        // (ca, an*ca)  [pad: (0, 3e4)]
static __device__ __half  g_As[MAXB * 64];     // fp16(-2*cb*pred), row-swizzled (128B rows)
static __device__ __half  g_Bs[MAXC * 64];     // fp16(ca*all),     row-swizzled

// ---------------- helpers ----------------
__device__ __forceinline__ uint32_t smem_u32(const void* p) {
    uint32_t a;
    asm("{ .reg .u64 t; cvta.to.shared.u64 t, %1; cvt.u32.u64 %0, t; }" : "=r"(a) : "l"(p));
    return a;
}
__device__ __forceinline__ uint32_t h2(float a, float b) {
    __half2 v = __floats2half2_rn(a, b);
    return *(uint32_t*)&v;
}
__device__ __forceinline__ void ldm_x4(uint32_t* r, uint32_t addr) {
    asm volatile("ldmatrix.sync.aligned.m8n8.x4.shared.b16 {%0,%1,%2,%3}, [%4];"
                 : "=r"(r[0]), "=r"(r[1]), "=r"(r[2]), "=r"(r[3]) : "r"(addr));
}
__device__ __forceinline__ void mma_f16(float* c, const uint32_t* a,
                                        uint32_t b0, uint32_t b1) {
    asm volatile(
        "mma.sync.aligned.m16n8k16.row.col.f32.f16.f16.f32 "
        "{%0,%1,%2,%3}, {%4,%5,%6,%7}, {%8,%9}, {%0,%1,%2,%3};"
        : "+f"(c[0]), "+f"(c[1]), "+f"(c[2]), "+f"(c[3])
        : "r"(a[0]), "r"(a[1]), "r"(a[2]), "r"(a[3]), "r"(b0), "r"(b1));
}
__device__ __forceinline__ void cp_async16(uint32_t smem_addr, const void* gmem) {
    asm volatile("cp.async.cg.shared.global [%0], [%1], 16;"
                 :: "r"(smem_addr), "l"(gmem) : "memory");
}

// ---------------- prep: scale, convert to fp16, swizzle ----------------
__global__ void prep_kernel(const float* __restrict__ pred,
                            const float* __restrict__ tgt,
                            const float* __restrict__ all,
                            int B, int C, int Bp, int Cp) {
    int gid  = blockIdx.x * blockDim.x + threadIdx.x;
    int r    = gid >> 3;
    int lane = gid & 7;   // covers k = 8*lane .. 8*lane+7 (one 16B chunk)
    if (gid == 0) g_hsum = 0.0;

    // ---- columns (all_embs) ----
    if (r < Cp) {
        char* dst = (char*)g_Bs + (size_t)r * 128;
        uint32_t so = (uint32_t)((lane ^ (r & 7)) << 4);
        if (r < C) {
            float4 a0 = ((const float4*)(all + (size_t)r * 64))[lane * 2];
            float4 a1 = ((const float4*)(all + (size_t)r * 64))[lane * 2 + 1];
            float s = 0.f;
            s = fmaf(a0.x, a0.x, s); s = fmaf(a0.y, a0.y, s);
            s = fmaf(a0.z, a0.z, s); s = fmaf(a0.w, a0.w, s);
            s = fmaf(a1.x, a1.x, s); s = fmaf(a1.y, a1.y, s);
            s = fmaf(a1.z, a1.z, s); s = fmaf(a1.w, a1.w, s);
            s += __shfl_xor_sync(0xFFFFFFFFu, s, 1);
            s += __shfl_xor_sync(0xFFFFFFFFu, s, 2);
            s += __shfl_xor_sync(0xFFFFFFFFu, s, 4);
            float an = fminf(fmaxf(s, 0.f), 1.0f - BEPS);
            float ca = 1.0f / (1.0f - an);
            *(uint4*)(dst + so) = make_uint4(
                h2(ca*a0.x, ca*a0.y), h2(ca*a0.z, ca*a0.w),
                h2(ca*a1.x, ca*a1.y), h2(ca*a1.z, ca*a1.w));
            if (lane == 0) g_colp[r] = make_float2(ca, an * ca);
        } else {
            *(uint4*)(dst + so) = make_uint4(0u, 0u, 0u, 0u);
            if (lane == 0) g_colp[r] = make_float2(0.f, 3e4f);
        }
    }

    // ---- rows (pred / target) ----
    if (r < Bp) {
        char* dst = (char*)g_As + (size_t)r * 128;
        uint32_t so = (uint32_t)((lane ^ (r & 7)) << 4);
        if (r < B) {
            float4 p0 = ((const float4*)(pred + (size_t)r * 64))[lane * 2];
            float4 p1 = ((const float4*)(pred + (size_t)r * 64))[lane * 2 + 1];
            float4 t0 = ((const float4*)(tgt  + (size_t)r * 64))[lane * 2];
            float4 t1 = ((const float4*)(tgt  + (size_t)r * 64))[lane * 2 + 1];
            float pn = 0.f, tn = 0.f, sq = 0.f;
            pn = fmaf(p0.x,p0.x,pn); pn = fmaf(p0.y,p0.y,pn); pn = fmaf(p0.z,p0.z,pn); pn = fmaf(p0.w,p0.w,pn);
            pn = fmaf(p1.x,p1.x,pn); pn = fmaf(p1.y,p1.y,pn); pn = fmaf(p1.z,p1.z,pn); pn = fmaf(p1.w,p1.w,pn);
            tn = fmaf(t0.x,t0.x,tn); tn = fmaf(t0.y,t0.y,tn); tn = fmaf(t0.z,t0.z,tn); tn = fmaf(t0.w,t0.w,tn);
            tn = fmaf(t1.x,t1.x,tn); tn = fmaf(t1.y,t1.y,tn); tn = fmaf(t1.z,t1.z,tn); tn = fmaf(t1.w,t1.w,tn);
            float dx;
            dx = p0.x-t0.x; sq = fmaf(dx,dx,sq); dx = p0.y-t0.y; sq = fmaf(dx,dx,sq);
            dx = p0.z-t0.z; sq = fmaf(dx,dx,sq); dx = p0.w-t0.w; sq = fmaf(dx,dx,sq);
            dx = p1.x-t1.x; sq = fmaf(dx,dx,sq); dx = p1.y-t1.y; sq = fmaf(dx,dx,sq);
            dx = p1.z-t1.z; sq = fmaf(dx,dx,sq); dx = p1.w-t1.w; sq = fmaf(dx,dx,sq);
            pn += __shfl_xor_sync(0xFFFFFFFFu, pn, 1);
            pn += __shfl_xor_sync(0xFFFFFFFFu, pn, 2);
            pn += __shfl_xor_sync(0xFFFFFFFFu, pn, 4);
            tn += __shfl_xor_sync(0xFFFFFFFFu, tn, 1);
            tn += __shfl_xor_sync(0xFFFFFFFFu, tn, 2);
            tn += __shfl_xor_sync(0xFFFFFFFFu, tn, 4);
            sq += __shfl_xor_sync(0xFFFFFFFFu, sq, 1);
            sq += __shfl_xor_sync(0xFFFFFFFFu, sq, 2);
            sq += __shfl_xor_sync(0xFFFFFFFFu, sq, 4);
            pn = fminf(fmaxf(pn, 0.f), 1.0f - BEPS);
            tn = fminf(fmaxf(tn, 0.f), 1.0f - BEPS);
            float cb = 2.0f / (1.0f - pn);
            float m2cb = -2.0f * cb;
            *(uint4*)(dst + so) = make_uint4(
                h2(m2cb*p0.x, m2cb*p0.y), h2(m2cb*p0.z, m2cb*p0.w),
                h2(m2cb*p1.x, m2cb*p1.y), h2(m2cb*p1.z, m2cb*p1.w));
            if (lane == 0) {
                float x = 1.0f + 2.0f * sq / ((1.0f - pn) * (1.0f - tn));
                x = fmaxf(x, 1.0f + 1e-7f);
                float d2c = logf(x + sqrtf(x * x - 1.0f));
                g_rowp[r] = make_float4(pn * cb, cb, (d2c + MARGIN) * INV_LN2, 0.f);
            }
        } else {
            *(uint4*)(dst + so) = make_uint4(0u, 0u, 0u, 0u);
            if (lane == 0) g_rowp[r] = make_float4(0.f, 0.f, 0.f, 0.f);
        }
    }
}

// ---------------- main: mma.sync fp16 m16n8k16 ----------------
#define BM 128
#define BN 128
#define OFF_A    0        // 16384 B (128 rows x 128 B)
#define OFF_B    16384    // 16384 B
#define OFF_CP   32768    // float2[128]
#define OFF_RED  33792    // float[8]
#define SMEM_SZ  33856

__global__ __launch_bounds__(256, 2)
void poincare_mma_kernel(int B, int C) {
    extern __shared__ char smem[];
    const uint32_t sbase = smem_u32(smem);
    const int tid  = threadIdx.x;
    const int w    = tid >> 5;
    const int lane = tid & 31;
    const int bm   = blockIdx.y * BM;
    const int bn   = blockIdx.x * BN;
    const int wm   = w & 3;
    const int wn   = w >> 2;

    // ---- async tile copy (swizzle baked into gmem layout) ----
    {
        const char* srcA = (const char*)g_As + (size_t)bm * 128;
        const char* srcB = (const char*)g_Bs + (size_t)bn * 128;
#pragma unroll
        for (int i = 0; i < 4; i++) {
            int idx = tid + i * 256;                 // 16B-chunk index 0..1023
            cp_async16(sbase + OFF_A + (idx << 4), srcA + (idx << 4));
            cp_async16(sbase + OFF_B + (idx << 4), srcB + (idx << 4));
        }
        asm volatile("cp.async.commit_group;" ::: "memory");
    }
    if (tid < 128) {
        float2 cpv = g_colp[bn + tid];
        ((float2*)(smem + OFF_CP))[tid] = cpv;
    }
    asm volatile("cp.async.wait_group 0;" ::: "memory");
    __syncthreads();

    // ---- fragment addressing ----
    // generic: row = blk*16 + (lane&15); chunk = 2s + (lane>>4); swizzle by row&7
    const int rsel = lane & 15;
    const int csel = lane >> 4;
    const int rowA = wm * 32 + rsel;
    const int swA  = rowA & 7;
    const uint32_t baseA = sbase + OFF_A + (uint32_t)(rowA << 7);
    const int rowB = rsel;                  // + (wn*64 + jp*16) added below
    const uint32_t baseB = sbase + OFF_B + (uint32_t)((wn * 64 + rowB) << 7);

    float acc[2][8][4];
#pragma unroll
    for (int i = 0; i < 2; i++)
#pragma unroll
        for (int j = 0; j < 8; j++)
#pragma unroll
            for (int q = 0; q < 4; q++) acc[i][j][q] = 0.f;

#pragma unroll
    for (int s = 0; s < 4; s++) {
        uint32_t af[2][4];
#pragma unroll
        for (int i = 0; i < 2; i++)
            ldm_x4(af[i], baseA + (uint32_t)(i * 16 * 128)
                        + (uint32_t)((((2 * s + csel) ^ swA) << 4)));
        uint32_t bf[4][4];
#pragma unroll
        for (int jp = 0; jp < 4; jp++) {
            int rB = wn * 64 + jp * 16 + rsel;
            ldm_x4(bf[jp], baseB + (uint32_t)(jp * 16 * 128)
                         + (uint32_t)((((2 * s + csel) ^ (rB & 7)) << 4)));
        }
#pragma unroll
        for (int i = 0; i < 2; i++) {
#pragma unroll
            for (int jp = 0; jp < 4; jp++) {
                // r0={n0-7,k0-7} r1={n8-15,k0-7} r2={n0-7,k8-15} r3={n8-15,k8-15}
                mma_f16(acc[i][jp * 2],     af[i], bf[jp][0], bf[jp][2]);
                mma_f16(acc[i][jp * 2 + 1], af[i], bf[jp][1], bf[jp][3]);
            }
        }
    }

    // ---- extras k-step: adds cb*ca*(pn+an) ----
    float4 rp[4];
#pragma unroll
    for (int t = 0; t < 4; t++)
        rp[t] = g_rowp[bm + wm * 32 + (lane >> 2) + t * 8];

    {
        const bool k0lane = (lane & 3) == 0;
        const float2* cp = (const float2*)(smem + OFF_CP);
        uint32_t aex[2][4];
#pragma unroll
        for (int i = 0; i < 2; i++) {
            aex[i][0] = k0lane ? h2(rp[2 * i].x,     rp[2 * i].y)     : 0u;
            aex[i][1] = k0lane ? h2(rp[2 * i + 1].x, rp[2 * i + 1].y) : 0u;
            aex[i][2] = 0u;
            aex[i][3] = 0u;
        }
        uint32_t bex[8];
#pragma unroll
        for (int jn = 0; jn < 8; jn++) {
            float2 cc = cp[wn * 64 + jn * 8 + (lane >> 2)];
            bex[jn] = k0lane ? h2(cc.x, cc.y) : 0u;
        }
#pragma unroll
        for (int i = 0; i < 2; i++)
#pragma unroll
            for (int jn = 0; jn < 8; jn++)
                mma_f16(acc[i][jn], aex[i], bex[jn], 0u);
    }

    // ---- epilogue ----
    float hs = 0.f;
#pragma unroll
    for (int i = 0; i < 2; i++) {
#pragma unroll
        for (int j = 0; j < 8; j++) {
#pragma unroll
            for (int h = 0; h < 2; h++) {
                float sc2 = rp[2 * i + h].z;
#pragma unroll
                for (int q = 0; q < 2; q++) {
                    float e  = acc[i][j][h * 2 + q];
                    float g  = fmaxf(e, 0.f);
                    float tq = g * (g + 2.0f);
                    float st;  asm("sqrt.approx.f32 %0, %1;" : "=f"(st) : "f"(tq));
                    float arg = (g + 1.0f) + st;
                    float lg;  asm("lg2.approx.f32 %0, %1;" : "=f"(lg) : "f"(arg));
                    hs += fmaxf(sc2 - lg, 0.f);
                }
            }
        }
    }

    // ---- reduce ----
#pragma unroll
    for (int s = 16; s > 0; s >>= 1)
        hs += __shfl_xor_sync(0xFFFFFFFFu, hs, s);
    if (lane == 0) ((float*)(smem + OFF_RED))[w] = hs;
    __syncthreads();
    if (w == 0) {
        float v = (lane < 8) ? ((float*)(smem + OFF_RED))[lane] : 0.f;
#pragma unroll
        for (int s = 4; s > 0; s >>= 1)
            v += __shfl_xor_sync(0xFFFFFFFFu, v, s);
        if (lane == 0) atomicAdd(&g_hsum, (double)(v * LN2));
    }
}

__global__ void finalize_kernel(float* out, int B) {
    double h = g_hsum;
    out[0] = (float)((h - 0.1 * (double)B) / (double)B);
}

extern "C" void kernel_launch(void* const* d_in, const int* in_sizes, int n_in,
                              void* d_out, int out_size) {
    const float* pred = (const float*)d_in[0];
    const float* tgt  = (const float*)d_in[1];
    const float* all  = (const float*)d_in[2];
    float* out = (float*)d_out;

    int B = in_sizes[0] / 64;
    int C = in_sizes[2] / 64;
    int Bp = ((B + 127) / 128) * 128;
    int Cp = ((C + 127) / 128) * 128;

    cudaFuncSetAttribute(poincare_mma_kernel,
                         cudaFuncAttributeMaxDynamicSharedMemorySize, SMEM_SZ);

    int nthr = ((Bp > Cp) ? Bp : Cp) * 8;
    prep_kernel<<<(nthr + 255) / 256, 256>>>(pred, tgt, all, B, C, Bp, Cp);

    dim3 grid(Cp / BN, Bp / BM);
    poincare_mma_kernel<<<grid, 256, SMEM_SZ>>>(B, C);

    finalize_kernel<<<1, 1>>>(out, B);
}